// round 8
// baseline (speedup 1.0000x reference)
#include <cuda_runtime.h>
#include <cuda_bf16.h>

#define N_NODES 50000
#define N_EDGES 600000
#define F 128
#define NG 512

// ---------------- scratch (device globals; no allocation allowed) ----------
__device__ float g_bufA[(size_t)N_NODES * F];
__device__ float g_bufB[(size_t)N_NODES * F];
__device__ float g_t[(size_t)N_NODES * 2 * F];   // [p | q] per node
__device__ int   g_deg[N_NODES];
__device__ int   g_cur[N_NODES];
__device__ int   g_off[N_NODES + 1];
__device__ int   g_srcs[N_EDGES];
__device__ float g_pooled[NG * F];

// ---------------- CSR build --------------------------------------------------
__global__ void k_zero(int* deg, int* cur) {
    for (int i = blockIdx.x * blockDim.x + threadIdx.x; i < N_NODES;
         i += gridDim.x * blockDim.x) {
        deg[i] = 0;
        cur[i] = 0;
    }
}

// NOTE: edge_index is int32 on the wire (JAX default x64-disabled downcasts
// the reference's jnp.int64 to int32). All data-derived indices are guarded.
__global__ void k_hist(const int* __restrict__ ei, int* deg) {
    for (int e = blockIdx.x * blockDim.x + threadIdx.x; e < N_EDGES;
         e += gridDim.x * blockDim.x) {
        int dst = ei[N_EDGES + e];
        if ((unsigned)dst < (unsigned)N_NODES) atomicAdd(&deg[dst], 1);
    }
}

// single-block exclusive scan over degrees -> off, off[N] = total
__global__ void k_scan(const int* __restrict__ deg, int* off) {
    __shared__ int sh[1024];
    int tid = threadIdx.x;
    int carry = 0;
    for (int base = 0; base < N_NODES; base += 1024) {
        int v = (base + tid < N_NODES) ? deg[base + tid] : 0;
        sh[tid] = v;
        __syncthreads();
        for (int o = 1; o < 1024; o <<= 1) {
            int t = (tid >= o) ? sh[tid - o] : 0;
            __syncthreads();
            sh[tid] += t;
            __syncthreads();
        }
        int incl = sh[tid];
        if (base + tid < N_NODES) off[base + tid] = carry + incl - v;  // exclusive
        int blocktot = sh[1023];
        __syncthreads();
        carry += blocktot;
    }
    if (tid == 0) off[N_NODES] = carry;
}

__global__ void k_fill(const int* __restrict__ ei, const int* __restrict__ off,
                       int* cur, int* srcs) {
    for (int e = blockIdx.x * blockDim.x + threadIdx.x; e < N_EDGES;
         e += gridDim.x * blockDim.x) {
        int src = ei[e];
        int dst = ei[N_EDGES + e];
        if ((unsigned)src >= (unsigned)N_NODES) continue;
        if ((unsigned)dst >= (unsigned)N_NODES) continue;
        int p = atomicAdd(&cur[dst], 1);
        int pos = off[dst] + p;
        if ((unsigned)pos < (unsigned)N_EDGES) srcs[pos] = src;
    }
}

// ---------------- GEMM: t = A @ [Wl | Wr]  (M x 128 x 256) -------------------
// Block tile 64(M) x 64(N), K=128. 256 threads, 4x4 micro-tile per thread.
// blockIdx.y in [0,4): y<2 -> Wl half (cols [0,128)), y>=2 -> Wr half.
__global__ void k_gemm(const float* __restrict__ A,
                       const float* __restrict__ Wl, const float* __restrict__ Wr,
                       float* __restrict__ t) {
    __shared__ __align__(16) float As[16][64];
    __shared__ __align__(16) float Ws[16][68];  // 272B row stride (mult of 16B)

    int tid = threadIdx.x;
    int bm = blockIdx.x * 64;
    int bn_local = (blockIdx.y & 1) * 64;
    const float* W = (blockIdx.y < 2) ? Wl : Wr;

    int tx = tid & 15, ty = tid >> 4;
    int am = tid >> 2;          // 0..63
    int ak = (tid & 3) * 4;     // 0,4,8,12
    int wk = tid >> 4;          // 0..15
    int wn = (tid & 15) * 4;    // 0..60

    float acc[4][4];
#pragma unroll
    for (int i = 0; i < 4; i++)
#pragma unroll
        for (int j = 0; j < 4; j++) acc[i][j] = 0.f;

    for (int kk = 0; kk < F; kk += 16) {
        int arow = bm + am;
        float4 av = make_float4(0.f, 0.f, 0.f, 0.f);
        if (arow < N_NODES) av = *(const float4*)(A + (size_t)arow * F + kk + ak);
        As[ak + 0][am] = av.x;
        As[ak + 1][am] = av.y;
        As[ak + 2][am] = av.z;
        As[ak + 3][am] = av.w;

        float4 wv = *(const float4*)(W + (size_t)(kk + wk) * F + bn_local + wn);
        *(float4*)&Ws[wk][wn] = wv;
        __syncthreads();

#pragma unroll
        for (int k = 0; k < 16; k++) {
            float a[4], w[4];
#pragma unroll
            for (int i = 0; i < 4; i++) a[i] = As[k][ty * 4 + i];
#pragma unroll
            for (int j = 0; j < 4; j++) w[j] = Ws[k][tx * 4 + j];
#pragma unroll
            for (int i = 0; i < 4; i++)
#pragma unroll
                for (int j = 0; j < 4; j++) acc[i][j] += a[i] * w[j];
        }
        __syncthreads();
    }

    int cn = blockIdx.y * 64;
#pragma unroll
    for (int i = 0; i < 4; i++) {
        int row = bm + ty * 4 + i;
        if (row < N_NODES) {
#pragma unroll
            for (int j = 0; j < 4; j++) {
                t[(size_t)row * 256 + cn + tx * 4 + j] = acc[i][j];
            }
        }
    }
}

// ---------------- aggregate + combine + ReLU ---------------------------------
// out[i] = relu( mean_{src in N(i)} p[src] + q[i] + b ), p = t[:, :128], q = t[:,128:]
__global__ void k_agg(const float* __restrict__ t, const int* __restrict__ off,
                      const int* __restrict__ srcs, const float* __restrict__ bias,
                      float* __restrict__ out) {
    int i = blockIdx.x;
    int f = threadIdx.x;
    int s = off[i], e = off[i + 1];
    float acc = 0.f;
    for (int j = s; j < e; j++) {
        int src = srcs[j];
        acc += t[(size_t)src * 256 + f];
    }
    int d = e - s;
    float inv = 1.0f / (float)(d > 0 ? d : 1);
    float v = acc * inv + t[(size_t)i * 256 + 128 + f] + bias[f];
    out[(size_t)i * F + f] = fmaxf(v, 0.0f);
}

// ---------------- global mean pool (batch sorted -> binary search ranges) ----
__device__ __forceinline__ int lowerb(const int* b, int n, int key) {
    int lo = 0, hi = n;
    while (lo < hi) {
        int mid = (lo + hi) >> 1;
        if (b[mid] < key) lo = mid + 1;
        else hi = mid;
    }
    return lo;
}

__global__ void k_pool(const int* __restrict__ batch,
                       const float* __restrict__ h, float* __restrict__ pooled) {
    int g = blockIdx.x;
    int f = threadIdx.x;
    int start = lowerb(batch, N_NODES, g);
    int end = lowerb(batch, N_NODES, g + 1);
    float acc = 0.f;
    for (int i = start; i < end; i++) acc += h[(size_t)i * F + f];
    int cnt = end - start;
    pooled[g * F + f] = acc / (float)(cnt > 0 ? cnt : 1);
}

// ---------------- final MLP: out = (pooled@Wf1+bf1)@Wf2+bf2 ------------------
__global__ void k_mlp(const float* __restrict__ pooled,
                      const float* __restrict__ Wf1, const float* __restrict__ bf1,
                      const float* __restrict__ Wf2, const float* __restrict__ bf2,
                      float* __restrict__ out) {
    __shared__ float ps[128];
    __shared__ float es[128];
    int g = blockIdx.x, j = threadIdx.x;
    ps[j] = pooled[g * F + j];
    __syncthreads();
    float acc = bf1[j];
#pragma unroll 8
    for (int k = 0; k < 128; k++) acc += ps[k] * Wf1[k * 128 + j];
    es[j] = acc;
    __syncthreads();
    if (j < 2) {
        float o = bf2[j];
        for (int k = 0; k < 128; k++) o += es[k] * Wf2[k * 2 + j];
        out[g * 2 + j] = o;
    }
}

// ---------------- launch -----------------------------------------------------
extern "C" void kernel_launch(void* const* d_in, const int* in_sizes, int n_in,
                              void* d_out, int out_size) {
    const float* x = (const float*)d_in[0];
    const int* ei = (const int*)d_in[1];      // int32! (JAX x64 disabled)
    const int* batch = (const int*)d_in[2];   // int32!

    // 16 parameter tensors follow {x, edge_index, batch[, num_graphs]}.
    int base = n_in - 16;

    const float* Wl[4] = {(const float*)d_in[base + 0], (const float*)d_in[base + 3],
                          (const float*)d_in[base + 6], (const float*)d_in[base + 9]};
    const float* Wr[4] = {(const float*)d_in[base + 1], (const float*)d_in[base + 4],
                          (const float*)d_in[base + 7], (const float*)d_in[base + 10]};
    const float* bb[4] = {(const float*)d_in[base + 2], (const float*)d_in[base + 5],
                          (const float*)d_in[base + 8], (const float*)d_in[base + 11]};
    const float* Wf1 = (const float*)d_in[base + 12];
    const float* bf1 = (const float*)d_in[base + 13];
    const float* Wf2 = (const float*)d_in[base + 14];
    const float* bf2 = (const float*)d_in[base + 15];
    float* out = (float*)d_out;

    // Resolve scratch addresses (pure queries; capture-safe, no allocation)
    float *bufA, *bufB, *t, *pooled;
    int *deg, *cur, *off, *srcs;
    cudaGetSymbolAddress((void**)&bufA, g_bufA);
    cudaGetSymbolAddress((void**)&bufB, g_bufB);
    cudaGetSymbolAddress((void**)&t, g_t);
    cudaGetSymbolAddress((void**)&pooled, g_pooled);
    cudaGetSymbolAddress((void**)&deg, g_deg);
    cudaGetSymbolAddress((void**)&cur, g_cur);
    cudaGetSymbolAddress((void**)&off, g_off);
    cudaGetSymbolAddress((void**)&srcs, g_srcs);

    // CSR build (once per call)
    k_zero<<<200, 256>>>(deg, cur);
    k_hist<<<1024, 256>>>(ei, deg);
    k_scan<<<1, 1024>>>(deg, off);
    k_fill<<<1024, 256>>>(ei, off, cur, srcs);

    dim3 gemm_grid((N_NODES + 63) / 64, 4);

    // layer 1: x -> bufA
    k_gemm<<<gemm_grid, 256>>>(x, Wl[0], Wr[0], t);
    k_agg<<<N_NODES, 128>>>(t, off, srcs, bb[0], bufA);
    // layer 2: bufA -> bufB
    k_gemm<<<gemm_grid, 256>>>(bufA, Wl[1], Wr[1], t);
    k_agg<<<N_NODES, 128>>>(t, off, srcs, bb[1], bufB);
    // layer 3: bufB -> bufA
    k_gemm<<<gemm_grid, 256>>>(bufB, Wl[2], Wr[2], t);
    k_agg<<<N_NODES, 128>>>(t, off, srcs, bb[2], bufA);
    // layer 4: bufA -> bufB
    k_gemm<<<gemm_grid, 256>>>(bufA, Wl[3], Wr[3], t);
    k_agg<<<N_NODES, 128>>>(t, off, srcs, bb[3], bufB);

    // pool + MLP
    k_pool<<<NG, 128>>>(batch, bufB, pooled);
    k_mlp<<<NG, 128>>>(pooled, Wf1, bf1, Wf2, bf2, out);
}

// round 9
// speedup vs baseline: 1.0613x; 1.0613x over previous
#include <cuda_runtime.h>
#include <cuda_bf16.h>
#include <cstdint>

#define N_NODES 50000
#define N_EDGES 600000
#define F 128
#define NG 512

// ---------------- scratch (device globals; no allocation allowed) ----------
__device__ float g_bufA[(size_t)N_NODES * F];
__device__ float g_bufB[(size_t)N_NODES * F];
__device__ float g_t[(size_t)N_NODES * 2 * F];   // [p | q] per node
__device__ int   g_deg[N_NODES];
__device__ int   g_cur[N_NODES];
__device__ int   g_off[N_NODES + 1];
__device__ int   g_srcs[N_EDGES];
__device__ float g_pooled[NG * F];

// ---------------- CSR build --------------------------------------------------
__global__ void k_zero(int* deg, int* cur) {
    for (int i = blockIdx.x * blockDim.x + threadIdx.x; i < N_NODES;
         i += gridDim.x * blockDim.x) {
        deg[i] = 0;
        cur[i] = 0;
    }
}

// edge_index is int32 on the wire (JAX x64 disabled). Guard data-derived idx.
__global__ void k_hist(const int* __restrict__ ei, int* deg) {
    for (int e = blockIdx.x * blockDim.x + threadIdx.x; e < N_EDGES;
         e += gridDim.x * blockDim.x) {
        int dst = ei[N_EDGES + e];
        if ((unsigned)dst < (unsigned)N_NODES) atomicAdd(&deg[dst], 1);
    }
}

// single-block exclusive scan (shuffle-based) -> off, off[N] = total
__global__ void k_scan(const int* __restrict__ deg, int* off) {
    __shared__ int warp_sums[32];
    __shared__ int carry_s;
    int tid = threadIdx.x;
    int lane = tid & 31, w = tid >> 5;  // 1024 threads = 32 warps
    if (tid == 0) carry_s = 0;
    __syncthreads();
    for (int base = 0; base < N_NODES; base += 1024) {
        int v = (base + tid < N_NODES) ? deg[base + tid] : 0;
        int s = v;  // inclusive warp scan
#pragma unroll
        for (int o = 1; o < 32; o <<= 1) {
            int t = __shfl_up_sync(0xFFFFFFFFu, s, o);
            if (lane >= o) s += t;
        }
        if (lane == 31) warp_sums[w] = s;
        __syncthreads();
        if (w == 0) {
            int ws = warp_sums[lane];
            int t = ws;
#pragma unroll
            for (int o = 1; o < 32; o <<= 1) {
                int u = __shfl_up_sync(0xFFFFFFFFu, t, o);
                if (lane >= o) t += u;
            }
            warp_sums[lane] = t - ws;  // exclusive warp offsets
        }
        __syncthreads();
        int excl = carry_s + warp_sums[w] + (s - v);
        if (base + tid < N_NODES) off[base + tid] = excl;
        __syncthreads();
        if (tid == 1023) carry_s = excl + v;
        __syncthreads();
    }
    if (tid == 0) off[N_NODES] = carry_s;
}

__global__ void k_fill(const int* __restrict__ ei, const int* __restrict__ off,
                       int* cur, int* srcs) {
    for (int e = blockIdx.x * blockDim.x + threadIdx.x; e < N_EDGES;
         e += gridDim.x * blockDim.x) {
        int src = ei[e];
        int dst = ei[N_EDGES + e];
        if ((unsigned)src >= (unsigned)N_NODES) continue;
        if ((unsigned)dst >= (unsigned)N_NODES) continue;
        int p = atomicAdd(&cur[dst], 1);
        int pos = off[dst] + p;
        if ((unsigned)pos < (unsigned)N_EDGES) srcs[pos] = src;
    }
}

// ---------------- TF32 tensor-core GEMM --------------------------------------
// t[:, y*128 : y*128+128] = A[M,128] @ W  (W = Wl if y==0 else Wr)
// Block: 128(M) x 128(N) x K=128, BK=32 chunks. 256 threads = 8 warps (4M x 2N).
// Warp tile 32x64 = 2 (m16) x 8 (n8) mma tiles, m16n8k8.
#define BM 128
#define BN 128
#define BK 32

__device__ __forceinline__ uint32_t f2tf(float f) {
    uint32_t r;
    asm("cvt.rna.tf32.f32 %0, %1;" : "=r"(r) : "f"(f));
    return r;
}

__device__ __forceinline__ void mma8(float* c, const uint32_t* a, const uint32_t* b) {
    asm volatile(
        "mma.sync.aligned.m16n8k8.row.col.f32.tf32.tf32.f32 "
        "{%0,%1,%2,%3}, {%4,%5,%6,%7}, {%8,%9}, {%0,%1,%2,%3};"
        : "+f"(c[0]), "+f"(c[1]), "+f"(c[2]), "+f"(c[3])
        : "r"(a[0]), "r"(a[1]), "r"(a[2]), "r"(a[3]), "r"(b[0]), "r"(b[1]));
}

__global__ __launch_bounds__(256) void k_gemm_tf32(
    const float* __restrict__ A, const float* __restrict__ Wl,
    const float* __restrict__ Wr, float* __restrict__ t) {
    __shared__ __align__(16) uint32_t sA[BM][BK + 4];   // stride 36: frag banks 4g+tg distinct
    __shared__ __align__(16) uint32_t sB[BK][BN + 8];   // stride 136: frag banks 8tg+g distinct

    const float* W = (blockIdx.y == 0) ? Wl : Wr;
    int bm = blockIdx.x * BM;
    int tid = threadIdx.x;
    int lane = tid & 31, wid = tid >> 5;
    int wm = (wid & 3) * 32;    // warp M offset
    int wn = (wid >> 2) * 64;   // warp N offset
    int g = lane >> 2, tg = lane & 3;

    float acc[2][8][4];
#pragma unroll
    for (int i = 0; i < 2; i++)
#pragma unroll
        for (int j = 0; j < 8; j++)
#pragma unroll
            for (int r = 0; r < 4; r++) acc[i][j][r] = 0.f;

    int ar = tid >> 1;            // A row 0..127
    int ac = (tid & 1) * 16;      // A col base within BK chunk
    int wr_ = tid >> 3;           // W k-row 0..31
    int wc = (tid & 7) * 16;      // W col base

    for (int kc = 0; kc < F; kc += BK) {
        // A chunk -> sA (convert to tf32)
        int arow = bm + ar;
#pragma unroll
        for (int v = 0; v < 4; v++) {
            float4 av = make_float4(0.f, 0.f, 0.f, 0.f);
            if (arow < N_NODES)
                av = *(const float4*)(A + (size_t)arow * F + kc + ac + v * 4);
            uint32_t* d = &sA[ar][ac + v * 4];
            d[0] = f2tf(av.x); d[1] = f2tf(av.y); d[2] = f2tf(av.z); d[3] = f2tf(av.w);
        }
        // W chunk -> sB
#pragma unroll
        for (int v = 0; v < 4; v++) {
            float4 wv = *(const float4*)(W + (size_t)(kc + wr_) * 128 + wc + v * 4);
            uint32_t* d = &sB[wr_][wc + v * 4];
            d[0] = f2tf(wv.x); d[1] = f2tf(wv.y); d[2] = f2tf(wv.z); d[3] = f2tf(wv.w);
        }
        __syncthreads();

#pragma unroll
        for (int kk = 0; kk < BK; kk += 8) {
            uint32_t afr[2][4];
#pragma unroll
            for (int i = 0; i < 2; i++) {
                int m0 = wm + i * 16;
                afr[i][0] = sA[m0 + g][kk + tg];
                afr[i][1] = sA[m0 + g + 8][kk + tg];
                afr[i][2] = sA[m0 + g][kk + tg + 4];
                afr[i][3] = sA[m0 + g + 8][kk + tg + 4];
            }
            uint32_t bfr[8][2];
#pragma unroll
            for (int j = 0; j < 8; j++) {
                int n0 = wn + j * 8;
                bfr[j][0] = sB[kk + tg][n0 + g];
                bfr[j][1] = sB[kk + tg + 4][n0 + g];
            }
#pragma unroll
            for (int i = 0; i < 2; i++)
#pragma unroll
                for (int j = 0; j < 8; j++) mma8(acc[i][j], afr[i], bfr[j]);
        }
        __syncthreads();
    }

    // epilogue: write to t[row, cn + col]
    int cn = blockIdx.y * 128;
#pragma unroll
    for (int i = 0; i < 2; i++) {
        int row0 = bm + wm + i * 16 + g;
        int row1 = row0 + 8;
#pragma unroll
        for (int j = 0; j < 8; j++) {
            int col = cn + wn + j * 8 + tg * 2;
            if (row0 < N_NODES)
                *(float2*)(t + (size_t)row0 * 256 + col) = make_float2(acc[i][j][0], acc[i][j][1]);
            if (row1 < N_NODES)
                *(float2*)(t + (size_t)row1 * 256 + col) = make_float2(acc[i][j][2], acc[i][j][3]);
        }
    }
}

// ---------------- aggregate + combine + ReLU ---------------------------------
__global__ void k_agg(const float* __restrict__ t, const int* __restrict__ off,
                      const int* __restrict__ srcs, const float* __restrict__ bias,
                      float* __restrict__ out) {
    int i = blockIdx.x;
    int f = threadIdx.x;
    int s = off[i], e = off[i + 1];
    float acc = 0.f;
    for (int j = s; j < e; j++) {
        int src = srcs[j];
        acc += t[(size_t)src * 256 + f];
    }
    int d = e - s;
    float inv = 1.0f / (float)(d > 0 ? d : 1);
    float v = acc * inv + t[(size_t)i * 256 + 128 + f] + bias[f];
    out[(size_t)i * F + f] = fmaxf(v, 0.0f);
}

// ---------------- global mean pool -------------------------------------------
__device__ __forceinline__ int lowerb(const int* b, int n, int key) {
    int lo = 0, hi = n;
    while (lo < hi) {
        int mid = (lo + hi) >> 1;
        if (b[mid] < key) lo = mid + 1;
        else hi = mid;
    }
    return lo;
}

__global__ void k_pool(const int* __restrict__ batch,
                       const float* __restrict__ h, float* __restrict__ pooled) {
    int g = blockIdx.x;
    int f = threadIdx.x;
    int start = lowerb(batch, N_NODES, g);
    int end = lowerb(batch, N_NODES, g + 1);
    float acc = 0.f;
    for (int i = start; i < end; i++) acc += h[(size_t)i * F + f];
    int cnt = end - start;
    pooled[g * F + f] = acc / (float)(cnt > 0 ? cnt : 1);
}

// ---------------- final MLP ---------------------------------------------------
__global__ void k_mlp(const float* __restrict__ pooled,
                      const float* __restrict__ Wf1, const float* __restrict__ bf1,
                      const float* __restrict__ Wf2, const float* __restrict__ bf2,
                      float* __restrict__ out) {
    __shared__ float ps[128];
    __shared__ float es[128];
    int g = blockIdx.x, j = threadIdx.x;
    ps[j] = pooled[g * F + j];
    __syncthreads();
    float acc = bf1[j];
#pragma unroll 8
    for (int k = 0; k < 128; k++) acc += ps[k] * Wf1[k * 128 + j];
    es[j] = acc;
    __syncthreads();
    if (j < 2) {
        float o = bf2[j];
        for (int k = 0; k < 128; k++) o += es[k] * Wf2[k * 2 + j];
        out[g * 2 + j] = o;
    }
}

// ---------------- launch -----------------------------------------------------
extern "C" void kernel_launch(void* const* d_in, const int* in_sizes, int n_in,
                              void* d_out, int out_size) {
    const float* x = (const float*)d_in[0];
    const int* ei = (const int*)d_in[1];      // int32 (JAX x64 disabled)
    const int* batch = (const int*)d_in[2];   // int32

    int base = n_in - 16;

    const float* Wl[4] = {(const float*)d_in[base + 0], (const float*)d_in[base + 3],
                          (const float*)d_in[base + 6], (const float*)d_in[base + 9]};
    const float* Wr[4] = {(const float*)d_in[base + 1], (const float*)d_in[base + 4],
                          (const float*)d_in[base + 7], (const float*)d_in[base + 10]};
    const float* bb[4] = {(const float*)d_in[base + 2], (const float*)d_in[base + 5],
                          (const float*)d_in[base + 8], (const float*)d_in[base + 11]};
    const float* Wf1 = (const float*)d_in[base + 12];
    const float* bf1 = (const float*)d_in[base + 13];
    const float* Wf2 = (const float*)d_in[base + 14];
    const float* bf2 = (const float*)d_in[base + 15];
    float* out = (float*)d_out;

    float *bufA, *bufB, *t, *pooled;
    int *deg, *cur, *off, *srcs;
    cudaGetSymbolAddress((void**)&bufA, g_bufA);
    cudaGetSymbolAddress((void**)&bufB, g_bufB);
    cudaGetSymbolAddress((void**)&t, g_t);
    cudaGetSymbolAddress((void**)&pooled, g_pooled);
    cudaGetSymbolAddress((void**)&deg, g_deg);
    cudaGetSymbolAddress((void**)&cur, g_cur);
    cudaGetSymbolAddress((void**)&off, g_off);
    cudaGetSymbolAddress((void**)&srcs, g_srcs);

    // CSR build
    k_zero<<<200, 256>>>(deg, cur);
    k_hist<<<1024, 256>>>(ei, deg);
    k_scan<<<1, 1024>>>(deg, off);
    k_fill<<<1024, 256>>>(ei, off, cur, srcs);

    dim3 gg((N_NODES + BM - 1) / BM, 2);

    // layer 1: x -> bufA
    k_gemm_tf32<<<gg, 256>>>(x, Wl[0], Wr[0], t);
    k_agg<<<N_NODES, 128>>>(t, off, srcs, bb[0], bufA);
    // layer 2
    k_gemm_tf32<<<gg, 256>>>(bufA, Wl[1], Wr[1], t);
    k_agg<<<N_NODES, 128>>>(t, off, srcs, bb[1], bufB);
    // layer 3
    k_gemm_tf32<<<gg, 256>>>(bufB, Wl[2], Wr[2], t);
    k_agg<<<N_NODES, 128>>>(t, off, srcs, bb[2], bufA);
    // layer 4
    k_gemm_tf32<<<gg, 256>>>(bufA, Wl[3], Wr[3], t);
    k_agg<<<N_NODES, 128>>>(t, off, srcs, bb[3], bufB);

    // pool + MLP
    k_pool<<<NG, 128>>>(batch, bufB, pooled);
    k_mlp<<<NG, 128>>>(pooled, Wf1, bf1, Wf2, bf2, out);
}